// round 8
// baseline (speedup 1.0000x reference)
#include <cuda_runtime.h>
#include <cuda_bf16.h>
#include <cstdint>

// PairwiseRepresentation: masked periodic pairwise distances.
//   positions      [B,N,3]   f32
//   neighbors      [B,N,K]   i32
//   neighbor_mask  [B,N,K]   f32
//   cell           [B,3,3]   f32
//   cell_offsets   [B,N,K,3] f32
//   out            [B,N,K]   f32
//
// R8: R7 frozen (256 thr / 3 CTAs per SM, simple 4-pair body, .cs streams,
// smem gather table) + the table fill rewritten division-free:
// 3 float4 loads = 12 floats = exactly 4 padded rows, so each thread-iter is
// 3 coalesced LDG.128 + 4 STS.128 with pure shifts — the fill ramp (worth
// ~2us in R5->R7) shrinks from 48 div/mod iterations to 4 lean ones.

#define MAX_ROWS (16 * 4096)
__device__ float4 g_pos4[MAX_ROWS];   // kept for ABI stability (unused fast path)

// ---------------- main kernel: fused fill + smem gather ----------------
__global__ __launch_bounds__(256, 3)
void pairwise_smem_kernel(const float*  __restrict__ positions,
                          const int*    __restrict__ neighbors,
                          const float*  __restrict__ mask,
                          const float*  __restrict__ cell,
                          const float*  __restrict__ offsets,
                          float*        __restrict__ out,
                          int N, int K, int rowsPer)
{
    extern __shared__ float4 s_tab[];          // N float4s (64KB for N=4096)

    const int b = blockIdx.y;

    // Division-free fused pad + fill.
    // Row-group g (4 rows = 12 floats = 3 float4s):
    //   in : pb4[3g], pb4[3g+1], pb4[3g+2]
    //   out: s_tab[4g + 0..3]
    {
        const float4* pb4 = (const float4*)(positions + (size_t)b * N * 3);
        const int nGroups = N >> 2;            // N % 4 == 0 on the fast path
        for (int g = threadIdx.x; g < nGroups; g += blockDim.x) {
            const float4 v0 = __ldg(&pb4[3 * g + 0]);  // r0.xyz r1.x
            const float4 v1 = __ldg(&pb4[3 * g + 1]);  // r1.yz  r2.xy
            const float4 v2 = __ldg(&pb4[3 * g + 2]);  // r2.z   r3.xyz
            s_tab[4 * g + 0] = make_float4(v0.x, v0.y, v0.z, 0.0f);
            s_tab[4 * g + 1] = make_float4(v0.w, v1.x, v1.y, 0.0f);
            s_tab[4 * g + 2] = make_float4(v1.z, v1.w, v2.x, 0.0f);
            s_tab[4 * g + 3] = make_float4(v2.y, v2.z, v2.w, 0.0f);
        }
        // tail rows (N % 4 != 0, generic path only)
        for (int r = (nGroups << 2) + threadIdx.x; r < N; r += blockDim.x) {
            const float* p = positions + (size_t)b * N * 3 + (size_t)r * 3;
            s_tab[r] = make_float4(__ldg(&p[0]), __ldg(&p[1]), __ldg(&p[2]), 0.0f);
        }
    }

    // Per-batch cell matrix -> registers.
    const float* cbp = cell + b * 9;
    const float c00 = __ldg(&cbp[0]), c01 = __ldg(&cbp[1]), c02 = __ldg(&cbp[2]);
    const float c10 = __ldg(&cbp[3]), c11 = __ldg(&cbp[4]), c12 = __ldg(&cbp[5]);
    const float c20 = __ldg(&cbp[6]), c21 = __ldg(&cbp[7]), c22 = __ldg(&cbp[8]);

    __syncthreads();

    const int warp = threadIdx.x >> 5;         // 0..7
    const int lane = threadIdx.x & 31;

    const int r0 = blockIdx.x * rowsPer;
    const int r1 = min(r0 + rowsPer, N);

    for (int r = r0 + warp; r < r1; r += 8) {
        const float4 pi4 = s_tab[r];
        const float pix = pi4.x, piy = pi4.y, piz = pi4.z;

        for (int k0 = lane * 4; k0 < K; k0 += 128) {
            const long base = ((long)b * N + r) * (long)K + k0;

            const int4   nb4 = __ldcs((const int4*)  (neighbors + base));
            const float4 mk4 = __ldcs((const float4*)(mask      + base));

            const float* offp = offsets + base * 3;
            const float4 o0 = __ldcs((const float4*)(offp + 0));
            const float4 o1 = __ldcs((const float4*)(offp + 4));
            const float4 o2 = __ldcs((const float4*)(offp + 8));

            const int   jj[4] = { nb4.x, nb4.y, nb4.z, nb4.w };
            const float ox[4] = { o0.x, o0.w, o1.z, o2.y };
            const float oy[4] = { o0.y, o1.x, o1.w, o2.z };
            const float oz[4] = { o0.z, o1.y, o2.x, o2.w };
            const float mm[4] = { mk4.x, mk4.y, mk4.z, mk4.w };

            float4 pj[4];
#pragma unroll
            for (int t = 0; t < 4; ++t) pj[t] = s_tab[jj[t]];

            float res[4];
#pragma unroll
            for (int t = 0; t < 4; ++t) {
                float dx = pj[t].x - pix;
                float dy = pj[t].y - piy;
                float dz = pj[t].z - piz;
                dx = fmaf(ox[t], c00, fmaf(oy[t], c10, fmaf(oz[t], c20, dx)));
                dy = fmaf(ox[t], c01, fmaf(oy[t], c11, fmaf(oz[t], c21, dy)));
                dz = fmaf(ox[t], c02, fmaf(oy[t], c12, fmaf(oz[t], c22, dz)));
                res[t] = (mm[t] > 0.0f)
                       ? sqrtf(fmaf(dx, dx, fmaf(dy, dy, dz * dz))) : 0.0f;
            }

            __stcs((float4*)(out + base),
                   make_float4(res[0], res[1], res[2], res[3]));
        }
    }
}

// ---------------- scalar fallback (oversized N or K%4 != 0) ----------------
__global__ __launch_bounds__(256)
void pairwise_fallback_kernel(const float* __restrict__ positions,
                              const int*   __restrict__ neighbors,
                              const float* __restrict__ mask,
                              const float* __restrict__ cell,
                              const float* __restrict__ offsets,
                              float*       __restrict__ out,
                              int N, int K, long total)
{
    long idx = (long)blockIdx.x * blockDim.x + threadIdx.x;
    if (idx >= total) return;
    const long row = idx / K;
    const int  b   = (int)(row / N);

    const float pix = positions[row * 3 + 0];
    const float piy = positions[row * 3 + 1];
    const float piz = positions[row * 3 + 2];
    const int j = neighbors[idx];
    const float* pj  = positions + ((size_t)b * N + j) * 3;
    const float* cbp = cell + b * 9;
    const float* op  = offsets + idx * 3;
    float dx = pj[0] - pix, dy = pj[1] - piy, dz = pj[2] - piz;
    dx = fmaf(op[0], cbp[0], fmaf(op[1], cbp[3], fmaf(op[2], cbp[6], dx)));
    dy = fmaf(op[0], cbp[1], fmaf(op[1], cbp[4], fmaf(op[2], cbp[7], dy)));
    dz = fmaf(op[0], cbp[2], fmaf(op[1], cbp[5], fmaf(op[2], cbp[8], dz)));
    out[idx] = (mask[idx] > 0.0f)
             ? sqrtf(fmaf(dx, dx, fmaf(dy, dy, dz * dz))) : 0.0f;
}

extern "C" void kernel_launch(void* const* d_in, const int* in_sizes, int n_in,
                              void* d_out, int out_size)
{
    const float* positions = (const float*)d_in[0];
    const int*   neighbors = (const int*)  d_in[1];
    const float* mask      = (const float*)d_in[2];
    const float* cell      = (const float*)d_in[3];
    const float* offsets   = (const float*)d_in[4];
    float*       out       = (float*)d_out;

    const int B      = in_sizes[3] / 9;
    const int n_rows = in_sizes[0] / 3;      // B*N
    const int N      = n_rows / B;
    const int K      = in_sizes[1] / n_rows;

    const size_t tabBytes = (size_t)N * sizeof(float4);

    if (tabBytes <= 65536 && (K % 4) == 0) {
        static bool attr_set = false;
        if (!attr_set) {
            cudaFuncSetAttribute(pairwise_smem_kernel,
                                 cudaFuncAttributeMaxDynamicSharedMemorySize, 65536);
            attr_set = true;
        }
        // 3 CTAs/SM x 148 SMs = 444 slots; S segments per batch.
        int S = 444 / B; if (S < 1) S = 1;
        const int rowsPer = (N + S - 1) / S;
        S = (N + rowsPer - 1) / rowsPer;     // trim empty CTAs
        dim3 grid(S, B);
        pairwise_smem_kernel<<<grid, 256, tabBytes>>>(positions, neighbors, mask,
                                                      cell, offsets, out,
                                                      N, K, rowsPer);
    } else {
        const long total = (long)n_rows * K;
        const int grid = (int)((total + 255) / 256);
        pairwise_fallback_kernel<<<grid, 256>>>(positions, neighbors, mask,
                                                cell, offsets, out, N, K, total);
    }
}

// round 9
// speedup vs baseline: 1.0469x; 1.0469x over previous
#include <cuda_runtime.h>
#include <cuda_bf16.h>
#include <cstdint>

// PairwiseRepresentation: masked periodic pairwise distances.
//   positions      [B,N,3]   f32
//   neighbors      [B,N,K]   i32
//   neighbor_mask  [B,N,K]   f32
//   cell           [B,3,3]   f32
//   cell_offsets   [B,N,K,3] f32
//   out            [B,N,K]   f32
//
// R9: SoA smem table (x[N], y[N], z[N] = 48KB) instead of padded float4
// (64KB): gathers shrink from LDS.128/16B (conflict deg ~7) to 3x LDS.32/12B
// (deg ~4), -25% smem traffic, and the smaller footprint allows 4 CTAs/SM
// (was 3) without any register squeeze. Fill stays division-free:
// 3 LDG.128 -> 3 STS.128 per 4-row group. Streaming path unchanged (R7/R8).

// ---------------- main kernel: SoA smem table ----------------
__global__ __launch_bounds__(256, 4)
void pairwise_soa_kernel(const float*  __restrict__ positions,
                         const int*    __restrict__ neighbors,
                         const float*  __restrict__ mask,
                         const float*  __restrict__ cell,
                         const float*  __restrict__ offsets,
                         float*        __restrict__ out,
                         int N, int K, int rowsPer)
{
    extern __shared__ float s_raw[];
    float* sx = s_raw;           // N floats
    float* sy = s_raw + N;       // N floats
    float* sz = s_raw + 2 * N;   // N floats

    const int b = blockIdx.y;

    // Division-free SoA fill. Group g = 4 rows = 12 floats = 3 float4 reads;
    // x/y/z quads of a group are contiguous -> 3 STS.128.
    {
        const float4* pb4 = (const float4*)(positions + (size_t)b * N * 3);
        const int nGroups = N >> 2;            // fast path requires N % 4 == 0
        for (int g = threadIdx.x; g < nGroups; g += blockDim.x) {
            const float4 v0 = __ldg(&pb4[3 * g + 0]);  // r0.xyz r1.x
            const float4 v1 = __ldg(&pb4[3 * g + 1]);  // r1.yz  r2.xy
            const float4 v2 = __ldg(&pb4[3 * g + 2]);  // r2.z   r3.xyz
            *(float4*)(sx + 4 * g) = make_float4(v0.x, v0.w, v1.z, v2.y);
            *(float4*)(sy + 4 * g) = make_float4(v0.y, v1.x, v1.w, v2.z);
            *(float4*)(sz + 4 * g) = make_float4(v0.z, v1.y, v2.x, v2.w);
        }
        for (int r = (nGroups << 2) + threadIdx.x; r < N; r += blockDim.x) {
            const float* p = positions + (size_t)b * N * 3 + (size_t)r * 3;
            sx[r] = __ldg(&p[0]); sy[r] = __ldg(&p[1]); sz[r] = __ldg(&p[2]);
        }
    }

    // Per-batch cell matrix -> registers.
    const float* cbp = cell + b * 9;
    const float c00 = __ldg(&cbp[0]), c01 = __ldg(&cbp[1]), c02 = __ldg(&cbp[2]);
    const float c10 = __ldg(&cbp[3]), c11 = __ldg(&cbp[4]), c12 = __ldg(&cbp[5]);
    const float c20 = __ldg(&cbp[6]), c21 = __ldg(&cbp[7]), c22 = __ldg(&cbp[8]);

    __syncthreads();

    const int warp = threadIdx.x >> 5;         // 0..7
    const int lane = threadIdx.x & 31;

    const int r0 = blockIdx.x * rowsPer;
    const int r1 = min(r0 + rowsPer, N);

    for (int r = r0 + warp; r < r1; r += 8) {
        const float pix = sx[r], piy = sy[r], piz = sz[r];

        for (int k0 = lane * 4; k0 < K; k0 += 128) {
            const long base = ((long)b * N + r) * (long)K + k0;

            const int4   nb4 = __ldcs((const int4*)  (neighbors + base));
            const float4 mk4 = __ldcs((const float4*)(mask      + base));

            const float* offp = offsets + base * 3;
            const float4 o0 = __ldcs((const float4*)(offp + 0));
            const float4 o1 = __ldcs((const float4*)(offp + 4));
            const float4 o2 = __ldcs((const float4*)(offp + 8));

            const int   jj[4] = { nb4.x, nb4.y, nb4.z, nb4.w };
            const float ox[4] = { o0.x, o0.w, o1.z, o2.y };
            const float oy[4] = { o0.y, o1.x, o1.w, o2.z };
            const float oz[4] = { o0.z, o1.y, o2.x, o2.w };
            const float mm[4] = { mk4.x, mk4.y, mk4.z, mk4.w };

            // SoA gathers: 3 x LDS.32 per neighbor.
            float gx[4], gy[4], gz[4];
#pragma unroll
            for (int t = 0; t < 4; ++t) {
                gx[t] = sx[jj[t]];
                gy[t] = sy[jj[t]];
                gz[t] = sz[jj[t]];
            }

            float res[4];
#pragma unroll
            for (int t = 0; t < 4; ++t) {
                float dx = gx[t] - pix;
                float dy = gy[t] - piy;
                float dz = gz[t] - piz;
                dx = fmaf(ox[t], c00, fmaf(oy[t], c10, fmaf(oz[t], c20, dx)));
                dy = fmaf(ox[t], c01, fmaf(oy[t], c11, fmaf(oz[t], c21, dy)));
                dz = fmaf(ox[t], c02, fmaf(oy[t], c12, fmaf(oz[t], c22, dz)));
                res[t] = (mm[t] > 0.0f)
                       ? sqrtf(fmaf(dx, dx, fmaf(dy, dy, dz * dz))) : 0.0f;
            }

            __stcs((float4*)(out + base),
                   make_float4(res[0], res[1], res[2], res[3]));
        }
    }
}

// ---------------- scalar fallback (oversized N or K%4 != 0) ----------------
__global__ __launch_bounds__(256)
void pairwise_fallback_kernel(const float* __restrict__ positions,
                              const int*   __restrict__ neighbors,
                              const float* __restrict__ mask,
                              const float* __restrict__ cell,
                              const float* __restrict__ offsets,
                              float*       __restrict__ out,
                              int N, int K, long total)
{
    long idx = (long)blockIdx.x * blockDim.x + threadIdx.x;
    if (idx >= total) return;
    const long row = idx / K;
    const int  b   = (int)(row / N);

    const float pix = positions[row * 3 + 0];
    const float piy = positions[row * 3 + 1];
    const float piz = positions[row * 3 + 2];
    const int j = neighbors[idx];
    const float* pj  = positions + ((size_t)b * N + j) * 3;
    const float* cbp = cell + b * 9;
    const float* op  = offsets + idx * 3;
    float dx = pj[0] - pix, dy = pj[1] - piy, dz = pj[2] - piz;
    dx = fmaf(op[0], cbp[0], fmaf(op[1], cbp[3], fmaf(op[2], cbp[6], dx)));
    dy = fmaf(op[0], cbp[1], fmaf(op[1], cbp[4], fmaf(op[2], cbp[7], dy)));
    dz = fmaf(op[0], cbp[2], fmaf(op[1], cbp[5], fmaf(op[2], cbp[8], dz)));
    out[idx] = (mask[idx] > 0.0f)
             ? sqrtf(fmaf(dx, dx, fmaf(dy, dy, dz * dz))) : 0.0f;
}

extern "C" void kernel_launch(void* const* d_in, const int* in_sizes, int n_in,
                              void* d_out, int out_size)
{
    const float* positions = (const float*)d_in[0];
    const int*   neighbors = (const int*)  d_in[1];
    const float* mask      = (const float*)d_in[2];
    const float* cell      = (const float*)d_in[3];
    const float* offsets   = (const float*)d_in[4];
    float*       out       = (float*)d_out;

    const int B      = in_sizes[3] / 9;
    const int n_rows = in_sizes[0] / 3;      // B*N
    const int N      = n_rows / B;
    const int K      = in_sizes[1] / n_rows;

    const size_t tabBytes = (size_t)N * 3 * sizeof(float);   // SoA: 48KB @ N=4096

    if (tabBytes <= 49152 && (K % 4) == 0) {
        static bool attr_set = false;
        if (!attr_set) {
            cudaFuncSetAttribute(pairwise_soa_kernel,
                                 cudaFuncAttributeMaxDynamicSharedMemorySize, 49152);
            attr_set = true;
        }
        // 4 CTAs/SM x 148 SMs = 592 slots; S segments per batch.
        int S = 592 / B; if (S < 1) S = 1;
        const int rowsPer = (N + S - 1) / S;
        S = (N + rowsPer - 1) / rowsPer;     // trim empty CTAs
        dim3 grid(S, B);
        pairwise_soa_kernel<<<grid, 256, tabBytes>>>(positions, neighbors, mask,
                                                     cell, offsets, out,
                                                     N, K, rowsPer);
    } else {
        const long total = (long)n_rows * K;
        const int grid = (int)((total + 255) / 256);
        pairwise_fallback_kernel<<<grid, 256>>>(positions, neighbors, mask,
                                                cell, offsets, out, N, K, total);
    }
}

// round 10
// speedup vs baseline: 1.2147x; 1.1603x over previous
#include <cuda_runtime.h>
#include <cuda_bf16.h>
#include <cstdint>

// PairwiseRepresentation: masked periodic pairwise distances.
//   positions      [B,N,3]   f32
//   neighbors      [B,N,K]   i32
//   neighbor_mask  [B,N,K]   f32
//   cell           [B,3,3]   f32
//   cell_offsets   [B,N,K,3] f32
//   out            [B,N,K]   f32
//
// R10: R9's SoA table (48KB: x[N],y[N],z[N]) kept, but CTAs widen to 512
// threads at 2 CTAs/SM — same 32 warps/SM as R9, half the table fills
// (288 CTAs instead of 592 -> 14MB instead of 28MB of L2 fill traffic,
// half the fill/sync ramps). Regs were already at the 64 cap in R9, so no
// new register squeeze. Streaming body unchanged (LDG.128 .cs, 4 pairs/lane,
// 3x LDS.32 SoA gathers).

// ---------------- main kernel: SoA smem table, 512 threads ----------------
__global__ __launch_bounds__(512, 2)
void pairwise_soa_kernel(const float*  __restrict__ positions,
                         const int*    __restrict__ neighbors,
                         const float*  __restrict__ mask,
                         const float*  __restrict__ cell,
                         const float*  __restrict__ offsets,
                         float*        __restrict__ out,
                         int N, int K, int rowsPer)
{
    extern __shared__ float s_raw[];
    float* sx = s_raw;           // N floats
    float* sy = s_raw + N;       // N floats
    float* sz = s_raw + 2 * N;   // N floats

    const int b = blockIdx.y;

    // Division-free SoA fill. Group g = 4 rows = 12 floats = 3 float4 reads;
    // x/y/z quads of a group are contiguous -> 3 STS.128.
    {
        const float4* pb4 = (const float4*)(positions + (size_t)b * N * 3);
        const int nGroups = N >> 2;            // fast path requires N % 4 == 0
        for (int g = threadIdx.x; g < nGroups; g += blockDim.x) {
            const float4 v0 = __ldg(&pb4[3 * g + 0]);  // r0.xyz r1.x
            const float4 v1 = __ldg(&pb4[3 * g + 1]);  // r1.yz  r2.xy
            const float4 v2 = __ldg(&pb4[3 * g + 2]);  // r2.z   r3.xyz
            *(float4*)(sx + 4 * g) = make_float4(v0.x, v0.w, v1.z, v2.y);
            *(float4*)(sy + 4 * g) = make_float4(v0.y, v1.x, v1.w, v2.z);
            *(float4*)(sz + 4 * g) = make_float4(v0.z, v1.y, v2.x, v2.w);
        }
        for (int r = (nGroups << 2) + threadIdx.x; r < N; r += blockDim.x) {
            const float* p = positions + (size_t)b * N * 3 + (size_t)r * 3;
            sx[r] = __ldg(&p[0]); sy[r] = __ldg(&p[1]); sz[r] = __ldg(&p[2]);
        }
    }

    // Per-batch cell matrix -> registers.
    const float* cbp = cell + b * 9;
    const float c00 = __ldg(&cbp[0]), c01 = __ldg(&cbp[1]), c02 = __ldg(&cbp[2]);
    const float c10 = __ldg(&cbp[3]), c11 = __ldg(&cbp[4]), c12 = __ldg(&cbp[5]);
    const float c20 = __ldg(&cbp[6]), c21 = __ldg(&cbp[7]), c22 = __ldg(&cbp[8]);

    __syncthreads();

    const int warp    = threadIdx.x >> 5;      // 0..15
    const int lane    = threadIdx.x & 31;
    const int n_warps = blockDim.x >> 5;       // 16

    const int r0 = blockIdx.x * rowsPer;
    const int r1 = min(r0 + rowsPer, N);

    for (int r = r0 + warp; r < r1; r += n_warps) {
        const float pix = sx[r], piy = sy[r], piz = sz[r];

        for (int k0 = lane * 4; k0 < K; k0 += 128) {
            const long base = ((long)b * N + r) * (long)K + k0;

            const int4   nb4 = __ldcs((const int4*)  (neighbors + base));
            const float4 mk4 = __ldcs((const float4*)(mask      + base));

            const float* offp = offsets + base * 3;
            const float4 o0 = __ldcs((const float4*)(offp + 0));
            const float4 o1 = __ldcs((const float4*)(offp + 4));
            const float4 o2 = __ldcs((const float4*)(offp + 8));

            const int   jj[4] = { nb4.x, nb4.y, nb4.z, nb4.w };
            const float ox[4] = { o0.x, o0.w, o1.z, o2.y };
            const float oy[4] = { o0.y, o1.x, o1.w, o2.z };
            const float oz[4] = { o0.z, o1.y, o2.x, o2.w };
            const float mm[4] = { mk4.x, mk4.y, mk4.z, mk4.w };

            // SoA gathers: 3 x LDS.32 per neighbor.
            float gx[4], gy[4], gz[4];
#pragma unroll
            for (int t = 0; t < 4; ++t) {
                gx[t] = sx[jj[t]];
                gy[t] = sy[jj[t]];
                gz[t] = sz[jj[t]];
            }

            float res[4];
#pragma unroll
            for (int t = 0; t < 4; ++t) {
                float dx = gx[t] - pix;
                float dy = gy[t] - piy;
                float dz = gz[t] - piz;
                dx = fmaf(ox[t], c00, fmaf(oy[t], c10, fmaf(oz[t], c20, dx)));
                dy = fmaf(ox[t], c01, fmaf(oy[t], c11, fmaf(oz[t], c21, dy)));
                dz = fmaf(ox[t], c02, fmaf(oy[t], c12, fmaf(oz[t], c22, dz)));
                res[t] = (mm[t] > 0.0f)
                       ? sqrtf(fmaf(dx, dx, fmaf(dy, dy, dz * dz))) : 0.0f;
            }

            __stcs((float4*)(out + base),
                   make_float4(res[0], res[1], res[2], res[3]));
        }
    }
}

// ---------------- scalar fallback (oversized N or K%4 != 0) ----------------
__global__ __launch_bounds__(256)
void pairwise_fallback_kernel(const float* __restrict__ positions,
                              const int*   __restrict__ neighbors,
                              const float* __restrict__ mask,
                              const float* __restrict__ cell,
                              const float* __restrict__ offsets,
                              float*       __restrict__ out,
                              int N, int K, long total)
{
    long idx = (long)blockIdx.x * blockDim.x + threadIdx.x;
    if (idx >= total) return;
    const long row = idx / K;
    const int  b   = (int)(row / N);

    const float pix = positions[row * 3 + 0];
    const float piy = positions[row * 3 + 1];
    const float piz = positions[row * 3 + 2];
    const int j = neighbors[idx];
    const float* pj  = positions + ((size_t)b * N + j) * 3;
    const float* cbp = cell + b * 9;
    const float* op  = offsets + idx * 3;
    float dx = pj[0] - pix, dy = pj[1] - piy, dz = pj[2] - piz;
    dx = fmaf(op[0], cbp[0], fmaf(op[1], cbp[3], fmaf(op[2], cbp[6], dx)));
    dy = fmaf(op[0], cbp[1], fmaf(op[1], cbp[4], fmaf(op[2], cbp[7], dy)));
    dz = fmaf(op[0], cbp[2], fmaf(op[1], cbp[5], fmaf(op[2], cbp[8], dz)));
    out[idx] = (mask[idx] > 0.0f)
             ? sqrtf(fmaf(dx, dx, fmaf(dy, dy, dz * dz))) : 0.0f;
}

extern "C" void kernel_launch(void* const* d_in, const int* in_sizes, int n_in,
                              void* d_out, int out_size)
{
    const float* positions = (const float*)d_in[0];
    const int*   neighbors = (const int*)  d_in[1];
    const float* mask      = (const float*)d_in[2];
    const float* cell      = (const float*)d_in[3];
    const float* offsets   = (const float*)d_in[4];
    float*       out       = (float*)d_out;

    const int B      = in_sizes[3] / 9;
    const int n_rows = in_sizes[0] / 3;      // B*N
    const int N      = n_rows / B;
    const int K      = in_sizes[1] / n_rows;

    const size_t tabBytes = (size_t)N * 3 * sizeof(float);   // SoA: 48KB @ N=4096

    if (tabBytes <= 49152 && (K % 4) == 0) {
        static bool attr_set = false;
        if (!attr_set) {
            cudaFuncSetAttribute(pairwise_soa_kernel,
                                 cudaFuncAttributeMaxDynamicSharedMemorySize, 49152);
            attr_set = true;
        }
        // 2 CTAs/SM x 148 SMs = 296 slots; S segments per batch.
        int S = 296 / B; if (S < 1) S = 1;
        const int rowsPer = (N + S - 1) / S;
        S = (N + rowsPer - 1) / rowsPer;     // trim empty CTAs
        dim3 grid(S, B);
        pairwise_soa_kernel<<<grid, 512, tabBytes>>>(positions, neighbors, mask,
                                                     cell, offsets, out,
                                                     N, K, rowsPer);
    } else {
        const long total = (long)n_rows * K;
        const int grid = (int)((total + 255) / 256);
        pairwise_fallback_kernel<<<grid, 256>>>(positions, neighbors, mask,
                                                cell, offsets, out, N, K, total);
    }
}